// round 16
// baseline (speedup 1.0000x reference)
#include <cuda_runtime.h>
#include <cstdint>

#define BB 256
#define CC 2048
#define HWN 49
#define KK 16
typedef unsigned long long ull;

// Static device scratch
__device__ __align__(16) float g_part[BB * 32 * 784]; // [b][slice<32][k*49+hw]
__device__ __align__(16) float g_fc16[BB * 784];      // [b][hw*16+k], BN'd, /49
__device__ __align__(16) float g_wT[CC * KK];         // [c][16]
__device__ float g_binv[KK], g_boff[KK];

__device__ __forceinline__ ull ffma2(ull a, ull b, ull c) {
    ull d;
    asm("fma.rn.f32x2 %0, %1, %2, %3;" : "=l"(d) : "l"(a), "l"(b), "l"(c));
    return d;
}
__device__ __forceinline__ ull pack2(float x, float y) {
    ull r;
    asm("mov.b64 %0, {%1, %2};" : "=l"(r) : "f"(x), "f"(y));
    return r;
}
__device__ __forceinline__ void unpack2(ull v, float& x, float& y) {
    asm("mov.b64 {%0, %1}, %2;" : "=f"(x), "=f"(y) : "l"(v));
}
__device__ __forceinline__ uint32_t smem_u32(const void* p) {
    uint32_t a;
    asm("{ .reg .u64 t; cvta.to.shared.u64 t, %1; cvt.u32.u64 %0, t; }"
        : "=r"(a) : "l"(p));
    return a;
}
__device__ __forceinline__ void mbar_init1(uint32_t mbar_a) {
    asm volatile("mbarrier.init.shared.b64 [%0], %1;" :: "r"(mbar_a), "r"(1));
}
__device__ __forceinline__ void mbar_expect(uint32_t mbar_a, uint32_t bytes) {
    asm volatile("mbarrier.arrive.expect_tx.shared.b64 _, [%0], %1;"
                 :: "r"(mbar_a), "r"(bytes));
}
__device__ __forceinline__ void mbar_wait0(uint32_t mbar_a) {
    uint32_t done;
    asm volatile(
        "{\n\t.reg .pred p;\n\t"
        "mbarrier.try_wait.parity.acquire.cta.shared::cta.b64 p, [%1], 0;\n\t"
        "selp.b32 %0, 1, 0, p;\n\t}"
        : "=r"(done) : "r"(mbar_a) : "memory");
    if (!done) {
        asm volatile(
            "{\n\t.reg .pred P1;\n\t"
            "W%=:\n\t"
            "mbarrier.try_wait.parity.acquire.cta.shared::cta.b64 P1, [%0], 0, 0x989680;\n\t"
            "@P1 bra.uni D%=;\n\t"
            "bra.uni W%=;\n\t"
            "D%=:\n\t}"
            :: "r"(mbar_a) : "memory");
    }
}
__device__ __forceinline__ void tma_bulk_1d(uint32_t dst_smem, const void* src,
                                            uint32_t bytes, uint32_t mbar_a) {
    asm volatile(
        "cp.async.bulk.shared::cta.global.mbarrier::complete_tx::bytes [%0], [%1], %2, [%3];"
        :: "r"(dst_smem), "l"(src), "r"(bytes), "r"(mbar_a) : "memory");
}

// ============================================================================
// K0: transpose weights -> g_wT[c][16]; BN constants (1/49 folded)
// ============================================================================
__global__ void k0_prep(const float* __restrict__ w16,
                        const float* __restrict__ bng, const float* __restrict__ bnb,
                        const float* __restrict__ bnm, const float* __restrict__ bnv) {
    int idx = blockIdx.x * 256 + threadIdx.x;
    if (idx < CC * KK) {
        int c = idx >> 4, k = idx & 15;
        g_wT[idx] = w16[k * CC + c];
    }
    if (blockIdx.x == 0 && threadIdx.x < KK) {
        int k = threadIdx.x;
        float iv = bng[k] * rsqrtf(bnv[k] + 1e-5f);
        g_binv[k] = iv * (1.0f / 49.0f);
        g_boff[k] = (bnb[k] - bnm[k] * iv) * (1.0f / 49.0f);
    }
}

// ============================================================================
// K1: partial conv, G=4 batch-grouped + k-split, staggered TMA (R12 design).
// Block = (q-slice of 128 c, b-quad within half). boff = batch offset.
// ============================================================================
#define K1_CCH (64 * HWN * 4)       // 12544 B: one (b, c-half) chunk
#define K1_FM_FLOATS (4 * 128 * HWN)
#define K1_SMEM (K1_FM_FLOATS * 4 + 128 * KK * 4 + 64)

__global__ __launch_bounds__(128) void k1_conv(const float* __restrict__ fm,
                                               int boff) {
    extern __shared__ __align__(16) float smem1[];
    float* fms = smem1;                              // [g][c(128)][49]
    float* wts = smem1 + K1_FM_FLOATS;               // [c][16]
    ull* mbars = (ull*)(wts + 128 * KK);             // [2]

    const int q = blockIdx.x;
    const int bp4 = boff + blockIdx.y * 4;
    const int tid = threadIdx.x;
    const int lane = tid & 31, wid = tid >> 5;
    const int s = wid & 1, h = wid >> 1;
    const bool hi = (lane < 17);
    const int cbase = q * 128;

    uint32_t mb0 = smem_u32(&mbars[0]);
    uint32_t mb1 = smem_u32(&mbars[1]);
    if (tid == 0) { mbar_init1(mb0); mbar_init1(mb1); }
    __syncthreads();
    if (tid == 0) {
        mbar_expect(mb0, 4 * K1_CCH);
        mbar_expect(mb1, 4 * K1_CCH);
#pragma unroll
        for (int g = 0; g < 4; g++) {
            const float* src = fm + (size_t)(bp4 + g) * (CC * HWN)
                                  + (size_t)cbase * HWN;
            tma_bulk_1d(smem_u32(fms + g * 128 * HWN), src, K1_CCH, mb0);
        }
#pragma unroll
        for (int g = 0; g < 4; g++) {
            const float* src = fm + (size_t)(bp4 + g) * (CC * HWN)
                                  + (size_t)(cbase + 64) * HWN;
            tma_bulk_1d(smem_u32(fms + g * 128 * HWN + 64 * HWN), src, K1_CCH, mb1);
        }
    }
    // stage weights (8KB) while TMA flies
    {
        const float4* src = (const float4*)(g_wT + cbase * KK);
        for (int i = tid; i < (128 * KK) / 4; i += 128) ((float4*)wts)[i] = src[i];
    }
    __syncthreads();

    mbar_wait0(s == 0 ? mb0 : mb1);

    ull accA[4][4], accB[4][4];   // [g][k-pair within 8-k half]
#pragma unroll
    for (int g = 0; g < 4; g++)
#pragma unroll
        for (int p = 0; p < 4; p++) { accA[g][p] = 0ull; accB[g][p] = 0ull; }

    const int c0 = s * 64;
#pragma unroll 4
    for (int j = 0; j < 64; j++) {
        const int c = c0 + j;
        ulonglong2 w01 = *(const ulonglong2*)(wts + c * KK + h * 8);
        ulonglong2 w23 = *(const ulonglong2*)(wts + c * KK + h * 8 + 4);
        ull wq0 = w01.x, wq1 = w01.y, wq2 = w23.x, wq3 = w23.y;

#pragma unroll
        for (int g = 0; g < 4; g++) {
            const float* row = fms + g * 128 * HWN + c * HWN;
            float v0 = row[lane];
            float v1 = hi ? row[lane + 32] : 0.0f;
            ull vv0 = pack2(v0, v0), vv1 = pack2(v1, v1);
            accA[g][0] = ffma2(wq0, vv0, accA[g][0]);
            accB[g][0] = ffma2(wq0, vv1, accB[g][0]);
            accA[g][1] = ffma2(wq1, vv0, accA[g][1]);
            accB[g][1] = ffma2(wq1, vv1, accB[g][1]);
            accA[g][2] = ffma2(wq2, vv0, accA[g][2]);
            accB[g][2] = ffma2(wq2, vv1, accB[g][2]);
            accA[g][3] = ffma2(wq3, vv0, accA[g][3]);
            accB[g][3] = ffma2(wq3, vv1, accB[g][3]);
        }
    }

    const int slice = q * 2 + s;
#pragma unroll
    for (int g = 0; g < 4; g++) {
        float* dst = g_part + ((size_t)(bp4 + g) * 32 + slice) * 784;
#pragma unroll
        for (int p = 0; p < 4; p++) {
            const int k0 = h * 8 + 2 * p;
            float x, y;
            unpack2(accA[g][p], x, y);
            dst[k0 * 49 + lane] = x;
            dst[(k0 + 1) * 49 + lane] = y;
            if (hi) {
                float xx, yy;
                unpack2(accB[g][p], xx, yy);
                dst[k0 * 49 + lane + 32] = xx;
                dst[(k0 + 1) * 49 + lane + 32] = yy;
            }
        }
    }
}

// ============================================================================
// K1b: reduce 32 partials, apply BN, relayout [k*49+hw] -> [hw*16+k]
// ============================================================================
__global__ __launch_bounds__(784) void k1b_reduce(int boff) {
    const int b = boff + blockIdx.x;
    const int o = threadIdx.x;
    const float* src = g_part + (size_t)b * 32 * 784;
    float s = 0.0f;
#pragma unroll
    for (int p = 0; p < 32; p++) s += src[p * 784 + o];
    int k = o / 49;
    int hw = o - k * 49;
    g_fc16[b * 784 + hw * 16 + k] = s * g_binv[k] + g_boff[k];
}

// ============================================================================
// K2: bilinear (proven R10 design). Block = (c-tile 512, b reversed within
// half), 128 thr, 4 c/thread, single mbarrier TMA stage, contiguous rows,
// fc quads via uniform LDS.128 depth-1 prefetch.
// ============================================================================
#define K2_TILE_BYTES (512 * HWN * 4)      // 100352
#define K2_FC_BYTES   (784 * 4)            // 3136
#define K2_SMEM (K2_TILE_BYTES + K2_FC_BYTES + 16)

__global__ __launch_bounds__(128, 2) void k2_bilinear(const float* __restrict__ fm,
                                                      float* __restrict__ out,
                                                      int boff, int nb) {
    extern __shared__ __align__(16) float smem[];
    float* fms = smem;                       // [512][49]
    float* fcs = smem + 512 * HWN;           // [hw][16]
    ull* mbar = (ull*)(smem + 512 * HWN + 784);

    const int tid = threadIdx.x;
    const int b = boff + (nb - 1) - blockIdx.y;   // reverse-b within half
    const int cbase = blockIdx.x * 512;

    uint32_t mbar_a = smem_u32(mbar);
    if (tid == 0) mbar_init1(mbar_a);
    __syncthreads();
    if (tid == 0) {
        mbar_expect(mbar_a, K2_TILE_BYTES + K2_FC_BYTES);
        tma_bulk_1d(smem_u32(fms),
                    fm + (size_t)b * (CC * HWN) + (size_t)cbase * HWN,
                    K2_TILE_BYTES, mbar_a);
        tma_bulk_1d(smem_u32(fcs), g_fc16 + (size_t)b * 784, K2_FC_BYTES, mbar_a);
    }
    mbar_wait0(mbar_a);

    const float* r0 = &fms[tid * HWN];
    const float* r1 = &fms[(tid + 128) * HWN];
    const float* r2 = &fms[(tid + 256) * HWN];
    const float* r3 = &fms[(tid + 384) * HWN];
    const ulonglong2* fq = (const ulonglong2*)fcs;

    ull acc[4][8];
#pragma unroll
    for (int i = 0; i < 4; i++)
#pragma unroll
        for (int j = 0; j < 8; j++) acc[i][j] = 0ull;

    ulonglong2 q0 = fq[0], q1 = fq[1], q2 = fq[2], q3 = fq[3];

#pragma unroll 7
    for (int hw = 0; hw < HWN; hw++) {
        ulonglong2 n0, n1, n2, n3;
        if (hw < HWN - 1) {
            n0 = fq[(hw + 1) * 4 + 0];
            n1 = fq[(hw + 1) * 4 + 1];
            n2 = fq[(hw + 1) * 4 + 2];
            n3 = fq[(hw + 1) * 4 + 3];
        }
        float va = r0[hw], vb = r1[hw], vc = r2[hw], vd = r3[hw];
        ull vva = pack2(va, va), vvb = pack2(vb, vb);
        ull vvc = pack2(vc, vc), vvd = pack2(vd, vd);

        acc[0][0] = ffma2(q0.x, vva, acc[0][0]);  acc[1][0] = ffma2(q0.x, vvb, acc[1][0]);
        acc[2][0] = ffma2(q0.x, vvc, acc[2][0]);  acc[3][0] = ffma2(q0.x, vvd, acc[3][0]);
        acc[0][1] = ffma2(q0.y, vva, acc[0][1]);  acc[1][1] = ffma2(q0.y, vvb, acc[1][1]);
        acc[2][1] = ffma2(q0.y, vvc, acc[2][1]);  acc[3][1] = ffma2(q0.y, vvd, acc[3][1]);
        acc[0][2] = ffma2(q1.x, vva, acc[0][2]);  acc[1][2] = ffma2(q1.x, vvb, acc[1][2]);
        acc[2][2] = ffma2(q1.x, vvc, acc[2][2]);  acc[3][2] = ffma2(q1.x, vvd, acc[3][2]);
        acc[0][3] = ffma2(q1.y, vva, acc[0][3]);  acc[1][3] = ffma2(q1.y, vvb, acc[1][3]);
        acc[2][3] = ffma2(q1.y, vvc, acc[2][3]);  acc[3][3] = ffma2(q1.y, vvd, acc[3][3]);
        acc[0][4] = ffma2(q2.x, vva, acc[0][4]);  acc[1][4] = ffma2(q2.x, vvb, acc[1][4]);
        acc[2][4] = ffma2(q2.x, vvc, acc[2][4]);  acc[3][4] = ffma2(q2.x, vvd, acc[3][4]);
        acc[0][5] = ffma2(q2.y, vva, acc[0][5]);  acc[1][5] = ffma2(q2.y, vvb, acc[1][5]);
        acc[2][5] = ffma2(q2.y, vvc, acc[2][5]);  acc[3][5] = ffma2(q2.y, vvd, acc[3][5]);
        acc[0][6] = ffma2(q3.x, vva, acc[0][6]);  acc[1][6] = ffma2(q3.x, vvb, acc[1][6]);
        acc[2][6] = ffma2(q3.x, vvc, acc[2][6]);  acc[3][6] = ffma2(q3.x, vvd, acc[3][6]);
        acc[0][7] = ffma2(q3.y, vva, acc[0][7]);  acc[1][7] = ffma2(q3.y, vvb, acc[1][7]);
        acc[2][7] = ffma2(q3.y, vvc, acc[2][7]);  acc[3][7] = ffma2(q3.y, vvd, acc[3][7]);

        q0 = n0; q1 = n1; q2 = n2; q3 = n3;
    }

#pragma unroll
    for (int i = 0; i < 4; i++) {
        float* ob = out + (size_t)b * 32768 + cbase + i * 128 + tid;
#pragma unroll
        for (int kp = 0; kp < 8; kp++) {
            float x, y;
            unpack2(acc[i][kp], x, y);
            ob[(2 * kp) * 2048] = x;
            ob[(2 * kp + 1) * 2048] = y;
        }
    }
}

extern "C" void kernel_launch(void* const* d_in, const int* in_sizes, int n_in,
                              void* d_out, int out_size) {
    const float* fm  = (const float*)d_in[0];  // [256,2048,7,7]
    const float* w16 = (const float*)d_in[1];  // [16,2048]
    const float* bng = (const float*)d_in[2];
    const float* bnb = (const float*)d_in[3];
    const float* bnm = (const float*)d_in[4];
    const float* bnv = (const float*)d_in[5];
    float* out = (float*)d_out;

    // One-time host resources (no device memory involved)
    static cudaStream_t s2 = nullptr;
    static cudaEvent_t eFork = nullptr, eJoin = nullptr;
    if (s2 == nullptr) {
        cudaStreamCreateWithFlags(&s2, cudaStreamNonBlocking);
        cudaEventCreateWithFlags(&eFork, cudaEventDisableTiming);
        cudaEventCreateWithFlags(&eJoin, cudaEventDisableTiming);
        cudaFuncSetAttribute(k1_conv, cudaFuncAttributeMaxDynamicSharedMemorySize,
                             K1_SMEM);
        cudaFuncSetAttribute(k2_bilinear, cudaFuncAttributeMaxDynamicSharedMemorySize,
                             K2_SMEM);
    }

    const int HB = BB / 2;  // 128 batches per half

    k0_prep<<<(CC * KK + 255) / 256, 256>>>(w16, bng, bnb, bnm, bnv);

    // fork: half 1 chain on s2, half 0 chain on the capture (default) stream
    cudaEventRecord(eFork, 0);
    cudaStreamWaitEvent(s2, eFork, 0);

    dim3 g1(16, HB / 4);   // 512 blocks per half
    dim3 g2(4, HB);        // 512 blocks per half

    // half 0 (default stream)
    k1_conv<<<g1, 128, K1_SMEM, 0>>>(fm, 0);
    k1b_reduce<<<HB, 784, 0, 0>>>(0);
    k2_bilinear<<<g2, 128, K2_SMEM, 0>>>(fm, out, 0, HB);

    // half 1 (s2)
    k1_conv<<<g1, 128, K1_SMEM, s2>>>(fm, HB);
    k1b_reduce<<<HB, 784, 0, s2>>>(HB);
    k2_bilinear<<<g2, 128, K2_SMEM, s2>>>(fm, out, HB, HB);

    // join
    cudaEventRecord(eJoin, s2);
    cudaStreamWaitEvent(0, eJoin, 0);
}